// round 6
// baseline (speedup 1.0000x reference)
#include <cuda_runtime.h>
#include <math.h>

#define BSZ 32
#define QN  600
#define NC  152
#define TT  32
#define NT  1024          // BSZ*TT
#define NR  19200         // BSZ*QN

// per-(which,batch,target) packed rowmin:  fmap(cost)<<32 | q
__device__ unsigned long long g_rowmin[2][BSZ][TT];

__device__ __forceinline__ unsigned fmap(float f) {
    unsigned b = __float_as_uint(f);
    return b ^ (unsigned)(((int)b >> 31) | 0x80000000);
}
__device__ __forceinline__ float funmap(unsigned m) {
    unsigned b = (m & 0x80000000u) ? (m ^ 0x80000000u) : ~m;
    return __uint_as_float(b);
}

// ===========================================================================
// Kernel 1: cost matrices + fused diagonal row-minima.
// 256 threads, 8 warps x 4 rows; smem 37.4KB.
// ===========================================================================
#define CTH 256
#define RPW 4

struct CostSmem {
    float4 s_box[NT];            // cxcywh
    unsigned short s_id[NT];
    float  s_prob[32][NC];
};

__global__ __launch_bounds__(CTH, 5) void cost_kernel(
    const float* __restrict__ lg0, const float* __restrict__ lg1,
    const float* __restrict__ bx0, const float* __restrict__ bx1,
    const float* __restrict__ tb0, const float* __restrict__ tb1,
    const int*   __restrict__ id0, const int*   __restrict__ id1,
    float* __restrict__ out)
{
    __shared__ CostSmem sm;
    const int which = blockIdx.z;
    const float* __restrict__ logits = which ? lg1 : lg0;
    const float* __restrict__ boxes  = which ? bx1 : bx0;
    const float* __restrict__ tbbox  = which ? tb1 : tb0;
    const int*   __restrict__ tids   = which ? id1 : id0;
    float* __restrict__ C = out + (size_t)which * ((size_t)NR * NT);

    const int tid = threadIdx.x;
    for (int j = tid; j < NT; j += CTH) {
        sm.s_box[j] = *reinterpret_cast<const float4*>(tbbox + (size_t)j * 4);
        sm.s_id[j]  = (unsigned short)tids[j];
    }

    const int warp = tid >> 5, lane = tid & 31;
    const int row0 = blockIdx.x * 32 + warp * RPW;   // 4-row group; 600%4==0 so
    const int bb   = row0 / QN;                      // single batch per group

    float ocx[RPW], ocy[RPW], ow[RPW], oh[RPW];
    float ox0[RPW], oy0[RPW], ox1[RPW], oy1[RPW], oarea[RPW];

    #pragma unroll
    for (int rr = 0; rr < RPW; rr++) {
        const int row = row0 + rr;
        const float* lrow = logits + (size_t)row * NC;
        float r[5], m = -1e30f;
        #pragma unroll
        for (int jj = 0; jj < 5; jj++) {
            int k = lane + 32 * jj;
            r[jj] = (k < NC) ? lrow[k] : -1e30f;
            m = fmaxf(m, r[jj]);
        }
        #pragma unroll
        for (int o = 16; o; o >>= 1) m = fmaxf(m, __shfl_xor_sync(~0u, m, o));
        float s = 0.f;
        #pragma unroll
        for (int jj = 0; jj < 5; jj++) {
            int k = lane + 32 * jj;
            if (k < NC) { r[jj] = __expf(r[jj] - m); s += r[jj]; }
        }
        #pragma unroll
        for (int o = 16; o; o >>= 1) s += __shfl_xor_sync(~0u, s, o);
        const float inv = __fdividef(1.f, s);
        #pragma unroll
        for (int jj = 0; jj < 5; jj++) {
            int k = lane + 32 * jj;
            if (k < NC) sm.s_prob[warp*RPW + rr][k] = r[jj] * inv;
        }
        const float4 pb = *reinterpret_cast<const float4*>(boxes + (size_t)row * 4);
        ocx[rr] = pb.x; ocy[rr] = pb.y; ow[rr] = pb.z; oh[rr] = pb.w;
        ox0[rr] = pb.x - 0.5f*pb.z; oy0[rr] = pb.y - 0.5f*pb.w;
        ox1[rr] = pb.x + 0.5f*pb.z; oy1[rr] = pb.y + 0.5f*pb.w;
        oarea[rr] = (ox1[rr] - ox0[rr]) * (oy1[rr] - oy0[rr]);
    }
    __syncthreads();

    for (int j = lane, kk = 0; j < NT; j += 32, kk++) {
        const float4 tb = sm.s_box[j];
        const int    id = sm.s_id[j];
        const float tx0 = tb.x - 0.5f*tb.z, ty0 = tb.y - 0.5f*tb.w;
        const float tx1 = tb.x + 0.5f*tb.z, ty1 = tb.y + 0.5f*tb.w;
        const float ta  = (tx1 - tx0) * (ty1 - ty0);
        const bool diag = (kk == bb);
        float dmin = 1e30f; int dq = 0;
        #pragma unroll
        for (int rr = 0; rr < RPW; rr++) {
            float prob = sm.s_prob[warp*RPW + rr][id];
            float l1 = fabsf(ocx[rr]-tb.x) + fabsf(ocy[rr]-tb.y)
                     + fabsf(ow[rr]-tb.z)  + fabsf(oh[rr]-tb.w);
            float ltx = fmaxf(ox0[rr], tx0), lty = fmaxf(oy0[rr], ty0);
            float rbx = fminf(ox1[rr], tx1), rby = fminf(oy1[rr], ty1);
            float iw  = fmaxf(rbx - ltx, 0.f), ih = fmaxf(rby - lty, 0.f);
            float inter = iw * ih;
            float uni   = oarea[rr] + ta - inter;
            float cx0 = fminf(ox0[rr], tx0), cy0 = fminf(oy0[rr], ty0);
            float cx1 = fmaxf(ox1[rr], tx1), cy1 = fmaxf(oy1[rr], ty1);
            float ac  = fmaxf(cx1 - cx0, 0.f) * fmaxf(cy1 - cy0, 0.f);
            // iou - (ac-uni)/ac == (inter*ac - (ac-uni)*uni) / (uni*ac)
            float giou = __fdividef(inter*ac - (ac - uni)*uni, uni*ac);
            float val  = l1 - prob - giou;
            C[(size_t)(row0 + rr) * NT + j] = val;
            if (val < dmin) { dmin = val; dq = row0 + rr; }
        }
        if (diag) {
            unsigned long long key =
                ((unsigned long long)fmap(dmin) << 32) | (unsigned)(dq - bb*QN);
            atomicMin(&g_rowmin[which][bb][lane], key);
        }
    }
}

// ===========================================================================
// Kernel 2: exact JV finish. No tile staging: warm start from g_rowmin,
// Phase C reads its few cost rows straight from L2. 64 blocks x 256 thr.
// ===========================================================================
#define MTH 256
#define NW  8
#define KS  3

__global__ __launch_bounds__(MTH, 1) void match_kernel(
    const float* __restrict__ Cfull, float* __restrict__ outbase)
{
    __shared__ float u[34];
    __shared__ int   rowarg[TT];
    __shared__ int   unrows[TT];
    __shared__ int   nun_s, cnt;
    __shared__ int   sq[TT], sr[TT];
    __shared__ unsigned long long red[2][NW];
    __shared__ int   way[QN];
    __shared__ int   p[QN];

    const int b     = blockIdx.x & 31;
    const int which = blockIdx.x >> 5;
    const float* __restrict__ C = Cfull + (size_t)which * ((size_t)NR * NT);
    const int tid  = threadIdx.x;
    const int warp = tid >> 5;

    for (int j = tid; j < QN; j += MTH) p[j] = 0;
    if (tid < TT) {
        unsigned long long key = g_rowmin[which][b][tid];
        u[tid + 1]  = funmap((unsigned)(key >> 32));
        rowarg[tid] = (int)(unsigned)key;
    }
    __syncthreads();

    // greedy tight-edge warm start (serial, tiny)
    if (tid == 0) {
        int nun = 0;
        for (int i = 1; i <= TT; i++) {
            int q = rowarg[i - 1];
            if (p[q] == 0) p[q] = i;
            else unrows[nun++] = i;
        }
        nun_s = nun;
    }
    __syncthreads();
    const int nun = nun_s;

    // shortest augmenting paths for leftover rows; cost rows read from gmem
    const int c_[KS] = { tid, tid + MTH, tid + 2 * MTH };
    const float* cb = C + (size_t)b * QN * NT + b * TT;   // + q*NT + t
    const size_t coff[KS] = { (size_t)c_[0]*NT, (size_t)c_[1]*NT, (size_t)c_[2]*NT };
    float v_[KS] = {0.f, 0.f, 0.f};
    int par = 0;

    for (int ii = 0; ii < nun; ii++) {
        const int i = unrows[ii];
        float s_[KS] = {1e30f, 1e30f, 1e30f};
        int usedm = (c_[2] < QN) ? 0 : 4;
        int j0 = -1, i0 = i, jf;
        float off = 0.f;

        for (;;) {
            #pragma unroll
            for (int k = 0; k < KS; k++)
                if (j0 == c_[k]) usedm |= 1 << k;

            const float ui0p = u[i0] - off;
            const float* crow = cb + (i0 - 1);

            float lmin = 1e30f; int lidx = 0x7fffffff;
            #pragma unroll
            for (int k = 0; k < KS; k++) {
                if (!((usedm >> k) & 1)) {
                    float cur = crow[coff[k]] - ui0p - v_[k];
                    if (cur < s_[k]) { s_[k] = cur; way[c_[k]] = j0; }
                    if (s_[k] < lmin) { lmin = s_[k]; lidx = c_[k]; }
                }
            }
            unsigned mu   = fmap(lmin);
            unsigned wmin = __reduce_min_sync(~0u, mu);
            unsigned cand = (mu == wmin) ? (unsigned)lidx : 0xffffffffu;
            unsigned widx = __reduce_min_sync(~0u, cand);
            if ((tid & 31) == 0)
                red[par][warp] = ((unsigned long long)wmin << 32) | widx;
            __syncthreads();
            unsigned long long bp = red[par][0];
            #pragma unroll
            for (int w = 1; w < NW; w++) bp = min(bp, red[par][w]);
            par ^= 1;
            off = funmap((unsigned)(bp >> 32));
            const int bj = (int)(unsigned)bp;
            const int prj = p[bj];
            if (prj == 0) { jf = bj; break; }
            i0 = prj; j0 = bj;
        }

        #pragma unroll
        for (int k = 0; k < KS; k++) {
            if (((usedm >> k) & 1) && c_[k] < QN) {
                float dv = off - s_[k];
                v_[k] -= dv;
                u[p[c_[k]]] += dv;
            }
        }
        __syncthreads();
        if (tid == 0) {
            u[i] += off;
            int j = jf;
            for (;;) {
                int jp = way[j];
                p[j] = (jp < 0) ? i : p[jp];
                if (jp < 0) break;
                j = jp;
            }
        }
        __syncthreads();
    }

    // emit: compact assigned pairs, rank by column, write
    if (tid == 0) cnt = 0;
    __syncthreads();
    #pragma unroll
    for (int k = 0; k < KS; k++) {
        int q = c_[k];
        if (q < QN && p[q]) {
            int t = atomicAdd(&cnt, 1);
            sq[t] = q;
            sr[t] = p[q] - 1;
        }
    }
    __syncthreads();
    if (tid < TT) {
        int q = sq[tid], r = sr[tid];
        int rank = 0;
        #pragma unroll
        for (int o = 0; o < TT; o++)
            rank += (__shfl_sync(~0u, q, o) < q) ? 1 : 0;
        float* op = outbase + (size_t)2 * NR * NT + (size_t)which * 2 * NT; // ps/po
        float* ot = op + NT;                                                // ts/to
        op[b * TT + rank] = (float)q;
        ot[b * TT + rank] = (float)r;
    }
}

// ===========================================================================
extern "C" void kernel_launch(void* const* d_in, const int* in_sizes, int n_in,
                              void* d_out, int out_size) {
    const float* lg0 = (const float*)d_in[0];
    const float* lg1 = (const float*)d_in[1];
    const float* bx0 = (const float*)d_in[2];
    const float* bx1 = (const float*)d_in[3];
    const float* tb0 = (const float*)d_in[4];
    const float* tb1 = (const float*)d_in[5];
    const int*   id0 = (const int*)d_in[6];
    const int*   id1 = (const int*)d_in[7];
    float* out = (float*)d_out;

    void* sym = nullptr;
    cudaGetSymbolAddress(&sym, g_rowmin);
    cudaMemsetAsync(sym, 0xFF, sizeof(unsigned long long) * 2 * BSZ * TT);

    dim3 cg(NR / 32, 1, 2);
    cost_kernel<<<cg, CTH>>>(lg0, lg1, bx0, bx1, tb0, tb1, id0, id1, out);
    match_kernel<<<64, MTH>>>(out, out);
}

// round 7
// speedup vs baseline: 1.4185x; 1.4185x over previous
#include <cuda_runtime.h>
#include <math.h>

#define BSZ 32
#define QN  600
#define NC  152
#define TT  32
#define NT  1024          // BSZ*TT
#define NR  19200         // BSZ*QN

// per-(which,batch,target) packed rowmin:  fmap(cost)<<32 | q
__device__ unsigned long long g_rowmin[2][BSZ][TT];

__device__ __forceinline__ unsigned fmap(float f) {
    unsigned b = __float_as_uint(f);
    return b ^ (unsigned)(((int)b >> 31) | 0x80000000);
}
__device__ __forceinline__ float funmap(unsigned m) {
    unsigned b = (m & 0x80000000u) ? (m ^ 0x80000000u) : ~m;
    return __uint_as_float(m & 0x80000000u ? (m ^ 0x80000000u) : ~m);
}

// ===========================================================================
// Kernel 1: cost matrices + fused diagonal row-minima.
// 256 threads, 8 warps x 4 rows; smem 37.4KB; 64 regs (no spills).
// ===========================================================================
#define CTH 256
#define RPW 4

struct CostSmem {
    float4 s_box[NT];            // cxcywh
    unsigned short s_id[NT];
    float  s_prob[32][NC];
};

__global__ __launch_bounds__(CTH, 4) void cost_kernel(
    const float* __restrict__ lg0, const float* __restrict__ lg1,
    const float* __restrict__ bx0, const float* __restrict__ bx1,
    const float* __restrict__ tb0, const float* __restrict__ tb1,
    const int*   __restrict__ id0, const int*   __restrict__ id1,
    float* __restrict__ out)
{
    __shared__ CostSmem sm;
    const int which = blockIdx.z;
    const float* __restrict__ logits = which ? lg1 : lg0;
    const float* __restrict__ boxes  = which ? bx1 : bx0;
    const float* __restrict__ tbbox  = which ? tb1 : tb0;
    const int*   __restrict__ tids   = which ? id1 : id0;
    float* __restrict__ C = out + (size_t)which * ((size_t)NR * NT);

    const int tid = threadIdx.x;
    for (int j = tid; j < NT; j += CTH) {
        sm.s_box[j] = *reinterpret_cast<const float4*>(tbbox + (size_t)j * 4);
        sm.s_id[j]  = (unsigned short)tids[j];
    }

    const int warp = tid >> 5, lane = tid & 31;
    const int row0 = blockIdx.x * 32 + warp * RPW;   // 600%4==0 -> one batch/group
    const int bb   = row0 / QN;

    float ocx[RPW], ocy[RPW], ow[RPW], oh[RPW];
    float ox0[RPW], oy0[RPW], ox1[RPW], oy1[RPW], oarea[RPW];

    #pragma unroll
    for (int rr = 0; rr < RPW; rr++) {
        const int row = row0 + rr;
        const float* lrow = logits + (size_t)row * NC;
        float r[5], m = -1e30f;
        #pragma unroll
        for (int jj = 0; jj < 5; jj++) {
            int k = lane + 32 * jj;
            r[jj] = (k < NC) ? lrow[k] : -1e30f;
            m = fmaxf(m, r[jj]);
        }
        #pragma unroll
        for (int o = 16; o; o >>= 1) m = fmaxf(m, __shfl_xor_sync(~0u, m, o));
        float s = 0.f;
        #pragma unroll
        for (int jj = 0; jj < 5; jj++) {
            int k = lane + 32 * jj;
            if (k < NC) { r[jj] = __expf(r[jj] - m); s += r[jj]; }
        }
        #pragma unroll
        for (int o = 16; o; o >>= 1) s += __shfl_xor_sync(~0u, s, o);
        const float inv = __fdividef(1.f, s);
        #pragma unroll
        for (int jj = 0; jj < 5; jj++) {
            int k = lane + 32 * jj;
            if (k < NC) sm.s_prob[warp*RPW + rr][k] = r[jj] * inv;
        }
        const float4 pb = *reinterpret_cast<const float4*>(boxes + (size_t)row * 4);
        ocx[rr] = pb.x; ocy[rr] = pb.y; ow[rr] = pb.z; oh[rr] = pb.w;
        ox0[rr] = pb.x - 0.5f*pb.z; oy0[rr] = pb.y - 0.5f*pb.w;
        ox1[rr] = pb.x + 0.5f*pb.z; oy1[rr] = pb.y + 0.5f*pb.w;
        oarea[rr] = (ox1[rr] - ox0[rr]) * (oy1[rr] - oy0[rr]);
    }
    __syncthreads();

    for (int j = lane, kk = 0; j < NT; j += 32, kk++) {
        const float4 tb = sm.s_box[j];
        const int    id = sm.s_id[j];
        const float tx0 = tb.x - 0.5f*tb.z, ty0 = tb.y - 0.5f*tb.w;
        const float tx1 = tb.x + 0.5f*tb.z, ty1 = tb.y + 0.5f*tb.w;
        const float ta  = (tx1 - tx0) * (ty1 - ty0);
        const bool diag = (kk == bb);
        float dmin = 1e30f; int dq = 0;
        #pragma unroll
        for (int rr = 0; rr < RPW; rr++) {
            float prob = sm.s_prob[warp*RPW + rr][id];
            float l1 = fabsf(ocx[rr]-tb.x) + fabsf(ocy[rr]-tb.y)
                     + fabsf(ow[rr]-tb.z)  + fabsf(oh[rr]-tb.w);
            float ltx = fmaxf(ox0[rr], tx0), lty = fmaxf(oy0[rr], ty0);
            float rbx = fminf(ox1[rr], tx1), rby = fminf(oy1[rr], ty1);
            float iw  = fmaxf(rbx - ltx, 0.f), ih = fmaxf(rby - lty, 0.f);
            float inter = iw * ih;
            float uni   = oarea[rr] + ta - inter;
            float cx0 = fminf(ox0[rr], tx0), cy0 = fminf(oy0[rr], ty0);
            float cx1 = fmaxf(ox1[rr], tx1), cy1 = fmaxf(oy1[rr], ty1);
            float ac  = fmaxf(cx1 - cx0, 0.f) * fmaxf(cy1 - cy0, 0.f);
            // iou - (ac-uni)/ac == (inter*ac - (ac-uni)*uni) / (uni*ac)
            float giou = __fdividef(inter*ac - (ac - uni)*uni, uni*ac);
            float val  = l1 - prob - giou;
            __stcs(&C[(size_t)(row0 + rr) * NT + j], val);   // streaming store
            if (val < dmin) { dmin = val; dq = row0 + rr; }
        }
        if (diag) {
            unsigned long long key =
                ((unsigned long long)fmap(dmin) << 32) | (unsigned)(dq - bb*QN);
            atomicMin(&g_rowmin[which][bb][lane], key);
        }
    }
}

// ===========================================================================
// Kernel 2: exact JV finish. Warm start from g_rowmin; no tile staging;
// Phase C reads its few cost rows from L2/DRAM. 64 blocks x 256 threads.
// ===========================================================================
#define MTH 256
#define NW  8
#define KS  3

__global__ __launch_bounds__(MTH, 1) void match_kernel(
    const float* __restrict__ Cfull, float* __restrict__ outbase)
{
    __shared__ float u[34];
    __shared__ int   rowarg[TT];
    __shared__ int   unrows[TT];
    __shared__ int   nun_s, cnt;
    __shared__ int   sq[TT], sr[TT];
    __shared__ unsigned long long red[2][NW];
    __shared__ int   way[QN];
    __shared__ int   p[QN];

    const int b     = blockIdx.x & 31;
    const int which = blockIdx.x >> 5;
    const float* __restrict__ C = Cfull + (size_t)which * ((size_t)NR * NT);
    const int tid  = threadIdx.x;
    const int warp = tid >> 5;

    for (int j = tid; j < QN; j += MTH) p[j] = 0;
    if (tid < TT) {
        unsigned long long key = g_rowmin[which][b][tid];
        u[tid + 1]  = funmap((unsigned)(key >> 32));
        rowarg[tid] = (int)(unsigned)key;
    }
    __syncthreads();

    // greedy tight-edge warm start (serial, tiny)
    if (tid == 0) {
        int nun = 0;
        for (int i = 1; i <= TT; i++) {
            int q = rowarg[i - 1];
            if (p[q] == 0) p[q] = i;
            else unrows[nun++] = i;
        }
        nun_s = nun;
    }
    __syncthreads();
    const int nun = nun_s;

    // shortest augmenting paths for leftover rows; cost rows read from gmem
    const int c_[KS] = { tid, tid + MTH, tid + 2 * MTH };
    const float* cb = C + (size_t)b * QN * NT + b * TT;   // + q*NT + t
    const size_t coff[KS] = { (size_t)c_[0]*NT, (size_t)c_[1]*NT, (size_t)c_[2]*NT };
    float v_[KS] = {0.f, 0.f, 0.f};
    int par = 0;

    for (int ii = 0; ii < nun; ii++) {
        const int i = unrows[ii];
        float s_[KS] = {1e30f, 1e30f, 1e30f};
        int usedm = (c_[2] < QN) ? 0 : 4;
        int j0 = -1, i0 = i, jf;
        float off = 0.f;

        for (;;) {
            #pragma unroll
            for (int k = 0; k < KS; k++)
                if (j0 == c_[k]) usedm |= 1 << k;

            const float ui0p = u[i0] - off;
            const float* crow = cb + (i0 - 1);

            float lmin = 1e30f; int lidx = 0x7fffffff;
            #pragma unroll
            for (int k = 0; k < KS; k++) {
                if (!((usedm >> k) & 1)) {
                    float cur = crow[coff[k]] - ui0p - v_[k];
                    if (cur < s_[k]) { s_[k] = cur; way[c_[k]] = j0; }
                    if (s_[k] < lmin) { lmin = s_[k]; lidx = c_[k]; }
                }
            }
            unsigned mu   = fmap(lmin);
            unsigned wmin = __reduce_min_sync(~0u, mu);
            unsigned cand = (mu == wmin) ? (unsigned)lidx : 0xffffffffu;
            unsigned widx = __reduce_min_sync(~0u, cand);
            if ((tid & 31) == 0)
                red[par][warp] = ((unsigned long long)wmin << 32) | widx;
            __syncthreads();
            unsigned long long bp = red[par][0];
            #pragma unroll
            for (int w = 1; w < NW; w++) bp = min(bp, red[par][w]);
            par ^= 1;
            off = funmap((unsigned)(bp >> 32));
            const int bj = (int)(unsigned)bp;
            const int prj = p[bj];
            if (prj == 0) { jf = bj; break; }
            i0 = prj; j0 = bj;
        }

        #pragma unroll
        for (int k = 0; k < KS; k++) {
            if (((usedm >> k) & 1) && c_[k] < QN) {
                float dv = off - s_[k];
                v_[k] -= dv;
                u[p[c_[k]]] += dv;
            }
        }
        __syncthreads();
        if (tid == 0) {
            u[i] += off;
            int j = jf;
            for (;;) {
                int jp = way[j];
                p[j] = (jp < 0) ? i : p[jp];
                if (jp < 0) break;
                j = jp;
            }
        }
        __syncthreads();
    }

    // emit: compact assigned pairs, rank by column, write
    if (tid == 0) cnt = 0;
    __syncthreads();
    #pragma unroll
    for (int k = 0; k < KS; k++) {
        int q = c_[k];
        if (q < QN && p[q]) {
            int t = atomicAdd(&cnt, 1);
            sq[t] = q;
            sr[t] = p[q] - 1;
        }
    }
    __syncthreads();
    if (tid < TT) {
        int q = sq[tid], r = sr[tid];
        int rank = 0;
        #pragma unroll
        for (int o = 0; o < TT; o++)
            rank += (__shfl_sync(~0u, q, o) < q) ? 1 : 0;
        float* op = outbase + (size_t)2 * NR * NT + (size_t)which * 2 * NT; // ps/po
        float* ot = op + NT;                                                // ts/to
        op[b * TT + rank] = (float)q;
        ot[b * TT + rank] = (float)r;
    }
}

// ===========================================================================
extern "C" void kernel_launch(void* const* d_in, const int* in_sizes, int n_in,
                              void* d_out, int out_size) {
    const float* lg0 = (const float*)d_in[0];
    const float* lg1 = (const float*)d_in[1];
    const float* bx0 = (const float*)d_in[2];
    const float* bx1 = (const float*)d_in[3];
    const float* tb0 = (const float*)d_in[4];
    const float* tb1 = (const float*)d_in[5];
    const int*   id0 = (const int*)d_in[6];
    const int*   id1 = (const int*)d_in[7];
    float* out = (float*)d_out;

    void* sym = nullptr;
    cudaGetSymbolAddress(&sym, g_rowmin);
    cudaMemsetAsync(sym, 0xFF, sizeof(unsigned long long) * 2 * BSZ * TT);

    dim3 cg(NR / 32, 1, 2);
    cost_kernel<<<cg, CTH>>>(lg0, lg1, bx0, bx1, tb0, tb1, id0, id1, out);
    match_kernel<<<64, MTH>>>(out, out);
}

// round 9
// speedup vs baseline: 1.7603x; 1.2410x over previous
#include <cuda_runtime.h>
#include <math.h>

#define BSZ 32
#define QN  600
#define NC  152
#define TT  32
#define NT  1024          // BSZ*TT
#define NR  19200         // BSZ*QN

#define CTH 256
#define RPW 4
#define NMATCH 64
#define NCOSTB 600        // cost blocks per which: NR / 32

// per-match-block diagonal tile: g_tile[blk][q][t]
__device__ float g_tile[NMATCH][QN][TT];

__device__ __forceinline__ unsigned fmap(float f) {
    unsigned b = __float_as_uint(f);
    return b ^ (unsigned)(((int)b >> 31) | 0x80000000);
}
__device__ __forceinline__ float funmap(unsigned m) {
    return __uint_as_float((m & 0x80000000u) ? (m ^ 0x80000000u) : ~m);
}

struct CostSmem {
    float4 s_box[NT];            // target cxcywh
    unsigned short s_id[NT];
    float  s_prob[32][NC];
};

#define NW 8
#define KS 3
struct MatchSmem {
    float  u[34];
    unsigned long long s_rm[TT];       // packed per-target rowmin
    unsigned long long red[2][NW];
    int    rowarg[TT];
    int    unrows[TT];
    int    nun_s, cnt;
    int    sq[TT], sr[TT];
    int    way[QN];
    int    p[QN];
    float4 t_box[TT];                  // target cxcywh
    float4 t_xy[TT];                   // target xyxy
    float  t_ta[TT];
    int    t_id[TT];
};

// ---------------------------------------------------------------------------
__device__ __forceinline__ float pair_cost(
    float ocx, float ocy, float ow, float oh,
    float ox0, float oy0, float ox1, float oy1, float oarea,
    float tcx, float tcy, float tw, float th,
    float tx0, float ty0, float tx1, float ty1, float ta, float prob)
{
    float l1 = fabsf(ocx - tcx) + fabsf(ocy - tcy)
             + fabsf(ow - tw)  + fabsf(oh - th);
    float ltx = fmaxf(ox0, tx0), lty = fmaxf(oy0, ty0);
    float rbx = fminf(ox1, tx1), rby = fminf(oy1, ty1);
    float iw  = fmaxf(rbx - ltx, 0.f), ih = fmaxf(rby - lty, 0.f);
    float inter = iw * ih;
    float uni   = oarea + ta - inter;
    float cx0 = fminf(ox0, tx0), cy0 = fminf(oy0, ty0);
    float cx1 = fmaxf(ox1, tx1), cy1 = fmaxf(oy1, ty1);
    float ac  = fmaxf(cx1 - cx0, 0.f) * fmaxf(cy1 - cy0, 0.f);
    float giou = __fdividef(inter*ac - (ac - uni)*uni, uni*ac);
    return l1 - prob - giou;
}

// ---------------------------------------------------------------------------
// Cost path: 8 warps x 4 rows, full C tile, streaming stores. No diag work.
// ---------------------------------------------------------------------------
__device__ void run_cost(
    CostSmem& sm, int xb, int which,
    const float* __restrict__ logits, const float* __restrict__ boxes,
    const float* __restrict__ tbbox,  const int* __restrict__ tids,
    float* __restrict__ out)
{
    float* __restrict__ C = out + (size_t)which * ((size_t)NR * NT);
    const int tid = threadIdx.x;

    for (int j = tid; j < NT; j += CTH) {
        sm.s_box[j] = *reinterpret_cast<const float4*>(tbbox + (size_t)j * 4);
        sm.s_id[j]  = (unsigned short)tids[j];
    }

    const int warp = tid >> 5, lane = tid & 31;
    const int row0 = xb * 32 + warp * RPW;

    float ocx[RPW], ocy[RPW], ow[RPW], oh[RPW];
    float ox0[RPW], oy0[RPW], ox1[RPW], oy1[RPW], oarea[RPW];

    #pragma unroll
    for (int rr = 0; rr < RPW; rr++) {
        const int row = row0 + rr;
        const float* lrow = logits + (size_t)row * NC;
        float r[5], m = -1e30f;
        #pragma unroll
        for (int jj = 0; jj < 5; jj++) {
            int k = lane + 32 * jj;
            r[jj] = (k < NC) ? lrow[k] : -1e30f;
            m = fmaxf(m, r[jj]);
        }
        #pragma unroll
        for (int o = 16; o; o >>= 1) m = fmaxf(m, __shfl_xor_sync(~0u, m, o));
        float s = 0.f;
        #pragma unroll
        for (int jj = 0; jj < 5; jj++) {
            int k = lane + 32 * jj;
            if (k < NC) { r[jj] = __expf(r[jj] - m); s += r[jj]; }
        }
        #pragma unroll
        for (int o = 16; o; o >>= 1) s += __shfl_xor_sync(~0u, s, o);
        const float inv = __fdividef(1.f, s);
        #pragma unroll
        for (int jj = 0; jj < 5; jj++) {
            int k = lane + 32 * jj;
            if (k < NC) sm.s_prob[warp*RPW + rr][k] = r[jj] * inv;
        }
        const float4 pb = *reinterpret_cast<const float4*>(boxes + (size_t)row * 4);
        ocx[rr] = pb.x; ocy[rr] = pb.y; ow[rr] = pb.z; oh[rr] = pb.w;
        ox0[rr] = pb.x - 0.5f*pb.z; oy0[rr] = pb.y - 0.5f*pb.w;
        ox1[rr] = pb.x + 0.5f*pb.z; oy1[rr] = pb.y + 0.5f*pb.w;
        oarea[rr] = (ox1[rr] - ox0[rr]) * (oy1[rr] - oy0[rr]);
    }
    __syncthreads();

    for (int j = lane; j < NT; j += 32) {
        const float4 tb = sm.s_box[j];
        const int    id = sm.s_id[j];
        const float tx0 = tb.x - 0.5f*tb.z, ty0 = tb.y - 0.5f*tb.w;
        const float tx1 = tb.x + 0.5f*tb.z, ty1 = tb.y + 0.5f*tb.w;
        const float ta  = (tx1 - tx0) * (ty1 - ty0);
        #pragma unroll
        for (int rr = 0; rr < RPW; rr++) {
            float prob = sm.s_prob[warp*RPW + rr][id];
            float val = pair_cost(ocx[rr], ocy[rr], ow[rr], oh[rr],
                                  ox0[rr], oy0[rr], ox1[rr], oy1[rr], oarea[rr],
                                  tb.x, tb.y, tb.z, tb.w,
                                  tx0, ty0, tx1, ty1, ta, prob);
            __stcs(&C[(size_t)(row0 + rr) * NT + j], val);
        }
    }
}

// ---------------------------------------------------------------------------
// Match path: self-computed diag tile -> g_tile, rowmin warm start, exact
// Dijkstra finish, ranked emit. Fully independent of cost blocks.
// ---------------------------------------------------------------------------
__device__ void run_match(
    MatchSmem& sm, int bi, int b, int which,
    const float* __restrict__ logits, const float* __restrict__ boxes,
    const float* __restrict__ tbbox,  const int* __restrict__ tids,
    float* __restrict__ outbase)
{
    const int tid  = threadIdx.x;
    const int warp = tid >> 5, lane = tid & 31;

    if (tid < TT) {
        int j = b * TT + tid;
        float4 t = *reinterpret_cast<const float4*>(tbbox + (size_t)j * 4);
        sm.t_box[tid] = t;
        float x0 = t.x - 0.5f*t.z, y0 = t.y - 0.5f*t.w;
        float x1 = t.x + 0.5f*t.z, y1 = t.y + 0.5f*t.w;
        sm.t_xy[tid] = make_float4(x0, y0, x1, y1);
        sm.t_ta[tid] = (x1 - x0) * (y1 - y0);
        sm.t_id[tid] = tids[j];
        sm.s_rm[tid] = ~0ull;
    }
    for (int j = tid; j < QN; j += CTH) sm.p[j] = 0;
    __syncthreads();

    // build tile: warp per prediction row q; lane = target t
    const int t = lane;
    const float4 tb  = sm.t_box[t];
    const float4 txy = sm.t_xy[t];
    const float  ta  = sm.t_ta[t];
    const int    tclass = sm.t_id[t];
    unsigned long long lmin = ~0ull;

    for (int k = 0; k < QN / NW; k++) {
        const int q = warp + NW * k;
        const float* lrow = logits + (size_t)(b * QN + q) * NC;
        float r[5], m = -1e30f;
        #pragma unroll
        for (int jj = 0; jj < 5; jj++) {
            int kk = lane + 32 * jj;
            r[jj] = (kk < NC) ? lrow[kk] : -1e30f;
            m = fmaxf(m, r[jj]);
        }
        #pragma unroll
        for (int o = 16; o; o >>= 1) m = fmaxf(m, __shfl_xor_sync(~0u, m, o));
        float s = 0.f;
        #pragma unroll
        for (int jj = 0; jj < 5; jj++) {
            int kk = lane + 32 * jj;
            if (kk < NC) s += __expf(r[jj] - m);
        }
        #pragma unroll
        for (int o = 16; o; o >>= 1) s += __shfl_xor_sync(~0u, s, o);
        const float inv = __fdividef(1.f, s);

        const float4 pb = *reinterpret_cast<const float4*>(boxes + (size_t)(b*QN + q)*4);
        const float ox0 = pb.x - 0.5f*pb.z, oy0 = pb.y - 0.5f*pb.w;
        const float ox1 = pb.x + 0.5f*pb.z, oy1 = pb.y + 0.5f*pb.w;
        const float oarea = (ox1 - ox0) * (oy1 - oy0);

        const float prob = __expf(lrow[tclass] - m) * inv;
        const float val = pair_cost(pb.x, pb.y, pb.z, pb.w,
                                    ox0, oy0, ox1, oy1, oarea,
                                    tb.x, tb.y, tb.z, tb.w,
                                    txy.x, txy.y, txy.z, txy.w, ta, prob);
        g_tile[bi][q][t] = val;                       // lanes t consecutive
        unsigned long long key = ((unsigned long long)fmap(val) << 32) | (unsigned)q;
        lmin = min(lmin, key);
    }
    atomicMin(&sm.s_rm[lane], lmin);                  // distinct addrs per lane
    __syncthreads();

    if (tid < TT) {
        unsigned long long key = sm.s_rm[tid];
        sm.u[tid + 1]  = funmap((unsigned)(key >> 32));
        sm.rowarg[tid] = (int)(unsigned)key;
    }
    __syncthreads();

    // greedy tight-edge warm start
    if (tid == 0) {
        int nun = 0;
        for (int i = 1; i <= TT; i++) {
            int q = sm.rowarg[i - 1];
            if (sm.p[q] == 0) sm.p[q] = i;
            else sm.unrows[nun++] = i;
        }
        sm.nun_s = nun;
    }
    __syncthreads();
    const int nun = sm.nun_s;

    // shortest augmenting paths; tile rows read from L1/L2 (just written here)
    const int c_[KS] = { tid, tid + CTH, tid + 2 * CTH };
    float v_[KS] = {0.f, 0.f, 0.f};
    int par = 0;

    for (int ii = 0; ii < nun; ii++) {
        const int i = sm.unrows[ii];
        float s_[KS] = {1e30f, 1e30f, 1e30f};
        int usedm = (c_[2] < QN) ? 0 : 4;
        int j0 = -1, i0 = i, jf;
        float off = 0.f;

        for (;;) {
            #pragma unroll
            for (int k = 0; k < KS; k++)
                if (j0 == c_[k]) usedm |= 1 << k;

            const float ui0p = sm.u[i0] - off;
            const int   trow = i0 - 1;

            float lm = 1e30f; int lidx = 0x7fffffff;
            #pragma unroll
            for (int k = 0; k < KS; k++) {
                if (!((usedm >> k) & 1)) {
                    float cur = g_tile[bi][c_[k]][trow] - ui0p - v_[k];
                    if (cur < s_[k]) { s_[k] = cur; sm.way[c_[k]] = j0; }
                    if (s_[k] < lm) { lm = s_[k]; lidx = c_[k]; }
                }
            }
            unsigned mu   = fmap(lm);
            unsigned wmin = __reduce_min_sync(~0u, mu);
            unsigned cand = (mu == wmin) ? (unsigned)lidx : 0xffffffffu;
            unsigned widx = __reduce_min_sync(~0u, cand);
            if (lane == 0)
                sm.red[par][warp] = ((unsigned long long)wmin << 32) | widx;
            __syncthreads();
            unsigned long long bp = sm.red[par][0];
            #pragma unroll
            for (int w = 1; w < NW; w++) bp = min(bp, sm.red[par][w]);
            par ^= 1;
            off = funmap((unsigned)(bp >> 32));
            const int bj = (int)(unsigned)bp;
            const int prj = sm.p[bj];
            if (prj == 0) { jf = bj; break; }
            i0 = prj; j0 = bj;
        }

        #pragma unroll
        for (int k = 0; k < KS; k++) {
            if (((usedm >> k) & 1) && c_[k] < QN) {
                float dv = off - s_[k];
                v_[k] -= dv;
                sm.u[sm.p[c_[k]]] += dv;
            }
        }
        __syncthreads();
        if (tid == 0) {
            sm.u[i] += off;
            int j = jf;
            for (;;) {
                int jp = sm.way[j];
                sm.p[j] = (jp < 0) ? i : sm.p[jp];
                if (jp < 0) break;
                j = jp;
            }
        }
        __syncthreads();
    }

    // emit: compact assigned pairs, rank by column, write
    if (tid == 0) sm.cnt = 0;
    __syncthreads();
    #pragma unroll
    for (int k = 0; k < KS; k++) {
        int q = c_[k];
        if (q < QN && sm.p[q]) {
            int tt = atomicAdd(&sm.cnt, 1);
            sm.sq[tt] = q;
            sm.sr[tt] = sm.p[q] - 1;
        }
    }
    __syncthreads();
    if (tid < TT) {
        int q = sm.sq[tid], r = sm.sr[tid];
        int rank = 0;
        #pragma unroll
        for (int o = 0; o < TT; o++)
            rank += (__shfl_sync(~0u, q, o) < q) ? 1 : 0;
        float* op = outbase + (size_t)2 * NR * NT + (size_t)which * 2 * NT; // ps/po
        float* ot = op + NT;                                                // ts/to
        op[b * TT + rank] = (float)q;
        ot[b * TT + rank] = (float)r;
    }
}

// ---------------------------------------------------------------------------
// Fused kernel: blocks [0,64) = match (wave-1, hidden under cost), rest cost.
// ---------------------------------------------------------------------------
__global__ __launch_bounds__(CTH, 4) void fused_kernel(
    const float* __restrict__ lg0, const float* __restrict__ lg1,
    const float* __restrict__ bx0, const float* __restrict__ bx1,
    const float* __restrict__ tb0, const float* __restrict__ tb1,
    const int*   __restrict__ id0, const int*   __restrict__ id1,
    float* __restrict__ out)
{
    extern __shared__ unsigned char smem_raw[];
    const int bi = blockIdx.x;

    if (bi < NMATCH) {
        const int b = bi & 31, which = bi >> 5;
        run_match(*reinterpret_cast<MatchSmem*>(smem_raw), bi, b, which,
                  which ? lg1 : lg0, which ? bx1 : bx0,
                  which ? tb1 : tb0, which ? id1 : id0, out);
    } else {
        const int cb = bi - NMATCH;
        const int which = cb / NCOSTB, xb = cb % NCOSTB;
        run_cost(*reinterpret_cast<CostSmem*>(smem_raw), xb, which,
                 which ? lg1 : lg0, which ? bx1 : bx0,
                 which ? tb1 : tb0, which ? id1 : id0, out);
    }
}

// ---------------------------------------------------------------------------
extern "C" void kernel_launch(void* const* d_in, const int* in_sizes, int n_in,
                              void* d_out, int out_size) {
    const float* lg0 = (const float*)d_in[0];
    const float* lg1 = (const float*)d_in[1];
    const float* bx0 = (const float*)d_in[2];
    const float* bx1 = (const float*)d_in[3];
    const float* tb0 = (const float*)d_in[4];
    const float* tb1 = (const float*)d_in[5];
    const int*   id0 = (const int*)d_in[6];
    const int*   id1 = (const int*)d_in[7];
    float* out = (float*)d_out;

    size_t smem = sizeof(CostSmem) > sizeof(MatchSmem)
                ? sizeof(CostSmem) : sizeof(MatchSmem);
    cudaFuncSetAttribute(fused_kernel,
                         cudaFuncAttributeMaxDynamicSharedMemorySize, (int)smem);

    fused_kernel<<<NMATCH + 2 * NCOSTB, CTH, smem>>>(
        lg0, lg1, bx0, bx1, tb0, tb1, id0, id1, out);
}

// round 10
// speedup vs baseline: 1.8948x; 1.0764x over previous
#include <cuda_runtime.h>
#include <math.h>

#define BSZ 32
#define QN  600
#define NC  152
#define TT  32
#define NT  1024          // BSZ*TT
#define NR  19200         // BSZ*QN

#define CTH 256
#define RPW 4
#define NMATCH 64
#define NCOSTB 600        // cost blocks per which: NR / 32

// per-match-block diagonal tile: g_tile[blk][q][t]
__device__ float g_tile[NMATCH][QN][TT];

__device__ __forceinline__ unsigned fmap(float f) {
    unsigned b = __float_as_uint(f);
    return b ^ (unsigned)(((int)b >> 31) | 0x80000000);
}
__device__ __forceinline__ float funmap(unsigned m) {
    return __uint_as_float((m & 0x80000000u) ? (m ^ 0x80000000u) : ~m);
}

struct CostSmem {
    float4 s_box[NT];            // target cxcywh
    float4 s_xy[NT];             // target xyxy
    float  s_ta[NT];             // target area
    unsigned char s_id[NT];
    float  s_prob[32][NC];
};

#define NW 8
#define KS 3
struct MatchSmem {
    float  u[34];
    unsigned long long s_rm[TT];       // packed per-target rowmin
    unsigned long long red[2][NW];
    int    rowarg[TT];
    int    unrows[TT];
    int    nun_s, cnt;
    int    sq[TT], sr[TT];
    int    way[QN];
    int    p[QN];
    float4 t_box[TT];                  // target cxcywh
    float4 t_xy[TT];                   // target xyxy
    float  t_ta[TT];
    int    t_id[TT];
};

// ---------------------------------------------------------------------------
// cost for one (pred, target) pair; enclosing box needs no clamp (w,h >= 0)
// ---------------------------------------------------------------------------
__device__ __forceinline__ float pair_cost(
    float ocx, float ocy, float ow, float oh,
    float ox0, float oy0, float ox1, float oy1, float oarea,
    float tcx, float tcy, float tw, float th,
    float tx0, float ty0, float tx1, float ty1, float ta, float prob)
{
    float l1 = fabsf(ocx - tcx) + fabsf(ocy - tcy)
             + fabsf(ow - tw)  + fabsf(oh - th);
    float ltx = fmaxf(ox0, tx0), lty = fmaxf(oy0, ty0);
    float rbx = fminf(ox1, tx1), rby = fminf(oy1, ty1);
    float iw  = fmaxf(rbx - ltx, 0.f), ih = fmaxf(rby - lty, 0.f);
    float inter = iw * ih;
    float uni   = oarea + ta - inter;
    float cx0 = fminf(ox0, tx0), cy0 = fminf(oy0, ty0);
    float cx1 = fmaxf(ox1, tx1), cy1 = fmaxf(oy1, ty1);
    float ac  = (cx1 - cx0) * (cy1 - cy0);          // >= 0 always
    float giou = __fdividef(inter*ac - (ac - uni)*uni, uni*ac);
    return l1 - prob - giou;
}

// ---------------------------------------------------------------------------
// Cost path: 8 warps x 4 rows; targets fully pre-staged (box, xyxy, area, id).
// ---------------------------------------------------------------------------
__device__ void run_cost(
    CostSmem& sm, int xb, int which,
    const float* __restrict__ logits, const float* __restrict__ boxes,
    const float* __restrict__ tbbox,  const int* __restrict__ tids,
    float* __restrict__ out)
{
    float* __restrict__ C = out + (size_t)which * ((size_t)NR * NT);
    const int tid = threadIdx.x;

    for (int j = tid; j < NT; j += CTH) {
        float4 t = *reinterpret_cast<const float4*>(tbbox + (size_t)j * 4);
        sm.s_box[j] = t;
        float x0 = t.x - 0.5f*t.z, y0 = t.y - 0.5f*t.w;
        float x1 = t.x + 0.5f*t.z, y1 = t.y + 0.5f*t.w;
        sm.s_xy[j] = make_float4(x0, y0, x1, y1);
        sm.s_ta[j] = (x1 - x0) * (y1 - y0);
        sm.s_id[j] = (unsigned char)tids[j];
    }

    const int warp = tid >> 5, lane = tid & 31;
    const int row0 = xb * 32 + warp * RPW;

    float ocx[RPW], ocy[RPW], ow[RPW], oh[RPW];
    float ox0[RPW], oy0[RPW], ox1[RPW], oy1[RPW], oarea[RPW];

    #pragma unroll
    for (int rr = 0; rr < RPW; rr++) {
        const int row = row0 + rr;
        const float* lrow = logits + (size_t)row * NC;
        float r[5], m = -1e30f;
        #pragma unroll
        for (int jj = 0; jj < 5; jj++) {
            int k = lane + 32 * jj;
            r[jj] = (k < NC) ? lrow[k] : -1e30f;
            m = fmaxf(m, r[jj]);
        }
        #pragma unroll
        for (int o = 16; o; o >>= 1) m = fmaxf(m, __shfl_xor_sync(~0u, m, o));
        float s = 0.f;
        #pragma unroll
        for (int jj = 0; jj < 5; jj++) {
            int k = lane + 32 * jj;
            if (k < NC) { r[jj] = __expf(r[jj] - m); s += r[jj]; }
        }
        #pragma unroll
        for (int o = 16; o; o >>= 1) s += __shfl_xor_sync(~0u, s, o);
        const float inv = __fdividef(1.f, s);
        #pragma unroll
        for (int jj = 0; jj < 5; jj++) {
            int k = lane + 32 * jj;
            if (k < NC) sm.s_prob[warp*RPW + rr][k] = r[jj] * inv;
        }
        const float4 pb = *reinterpret_cast<const float4*>(boxes + (size_t)row * 4);
        ocx[rr] = pb.x; ocy[rr] = pb.y; ow[rr] = pb.z; oh[rr] = pb.w;
        ox0[rr] = pb.x - 0.5f*pb.z; oy0[rr] = pb.y - 0.5f*pb.w;
        ox1[rr] = pb.x + 0.5f*pb.z; oy1[rr] = pb.y + 0.5f*pb.w;
        oarea[rr] = (ox1[rr] - ox0[rr]) * (oy1[rr] - oy0[rr]);
    }
    __syncthreads();

    for (int j = lane; j < NT; j += 32) {
        const float4 tb  = sm.s_box[j];
        const float4 txy = sm.s_xy[j];
        const float  ta  = sm.s_ta[j];
        const int    id  = sm.s_id[j];
        const int    wb4 = warp * RPW;
        float pr[RPW];
        #pragma unroll
        for (int rr = 0; rr < RPW; rr++) pr[rr] = sm.s_prob[wb4 + rr][id];
        #pragma unroll
        for (int rr = 0; rr < RPW; rr++) {
            float val = pair_cost(ocx[rr], ocy[rr], ow[rr], oh[rr],
                                  ox0[rr], oy0[rr], ox1[rr], oy1[rr], oarea[rr],
                                  tb.x, tb.y, tb.z, tb.w,
                                  txy.x, txy.y, txy.z, txy.w, ta, pr[rr]);
            __stcs(&C[(size_t)(row0 + rr) * NT + j], val);
        }
    }
}

// ---------------------------------------------------------------------------
// Match path: self-computed diag tile -> g_tile, rowmin warm start, exact
// Dijkstra finish, ranked emit. Fully independent of cost blocks.
// ---------------------------------------------------------------------------
__device__ void run_match(
    MatchSmem& sm, int bi, int b, int which,
    const float* __restrict__ logits, const float* __restrict__ boxes,
    const float* __restrict__ tbbox,  const int* __restrict__ tids,
    float* __restrict__ outbase)
{
    const int tid  = threadIdx.x;
    const int warp = tid >> 5, lane = tid & 31;

    if (tid < TT) {
        int j = b * TT + tid;
        float4 t = *reinterpret_cast<const float4*>(tbbox + (size_t)j * 4);
        sm.t_box[tid] = t;
        float x0 = t.x - 0.5f*t.z, y0 = t.y - 0.5f*t.w;
        float x1 = t.x + 0.5f*t.z, y1 = t.y + 0.5f*t.w;
        sm.t_xy[tid] = make_float4(x0, y0, x1, y1);
        sm.t_ta[tid] = (x1 - x0) * (y1 - y0);
        sm.t_id[tid] = tids[j];
        sm.s_rm[tid] = ~0ull;
    }
    for (int j = tid; j < QN; j += CTH) sm.p[j] = 0;
    __syncthreads();

    // build tile: warp per prediction row q; lane = target t
    const int t = lane;
    const float4 tb  = sm.t_box[t];
    const float4 txy = sm.t_xy[t];
    const float  ta  = sm.t_ta[t];
    const int    tclass = sm.t_id[t];
    unsigned long long lmin = ~0ull;

    for (int k = 0; k < QN / NW; k++) {
        const int q = warp + NW * k;
        const float* lrow = logits + (size_t)(b * QN + q) * NC;
        float r[5], m = -1e30f;
        #pragma unroll
        for (int jj = 0; jj < 5; jj++) {
            int kk = lane + 32 * jj;
            r[jj] = (kk < NC) ? lrow[kk] : -1e30f;
            m = fmaxf(m, r[jj]);
        }
        #pragma unroll
        for (int o = 16; o; o >>= 1) m = fmaxf(m, __shfl_xor_sync(~0u, m, o));
        float s = 0.f;
        #pragma unroll
        for (int jj = 0; jj < 5; jj++) {
            int kk = lane + 32 * jj;
            if (kk < NC) s += __expf(r[jj] - m);
        }
        #pragma unroll
        for (int o = 16; o; o >>= 1) s += __shfl_xor_sync(~0u, s, o);
        const float inv = __fdividef(1.f, s);

        const float4 pb = *reinterpret_cast<const float4*>(boxes + (size_t)(b*QN + q)*4);
        const float ox0 = pb.x - 0.5f*pb.z, oy0 = pb.y - 0.5f*pb.w;
        const float ox1 = pb.x + 0.5f*pb.z, oy1 = pb.y + 0.5f*pb.w;
        const float oarea = (ox1 - ox0) * (oy1 - oy0);

        const float prob = __expf(lrow[tclass] - m) * inv;
        const float val = pair_cost(pb.x, pb.y, pb.z, pb.w,
                                    ox0, oy0, ox1, oy1, oarea,
                                    tb.x, tb.y, tb.z, tb.w,
                                    txy.x, txy.y, txy.z, txy.w, ta, prob);
        g_tile[bi][q][t] = val;                       // lanes t consecutive
        unsigned long long key = ((unsigned long long)fmap(val) << 32) | (unsigned)q;
        lmin = min(lmin, key);
    }
    atomicMin(&sm.s_rm[lane], lmin);                  // distinct addrs per lane
    __syncthreads();

    if (tid < TT) {
        unsigned long long key = sm.s_rm[tid];
        sm.u[tid + 1]  = funmap((unsigned)(key >> 32));
        sm.rowarg[tid] = (int)(unsigned)key;
    }
    __syncthreads();

    // greedy tight-edge warm start
    if (tid == 0) {
        int nun = 0;
        for (int i = 1; i <= TT; i++) {
            int q = sm.rowarg[i - 1];
            if (sm.p[q] == 0) sm.p[q] = i;
            else sm.unrows[nun++] = i;
        }
        sm.nun_s = nun;
    }
    __syncthreads();
    const int nun = sm.nun_s;

    // shortest augmenting paths; tile rows read from L1/L2 (just written here)
    const int c_[KS] = { tid, tid + CTH, tid + 2 * CTH };
    float v_[KS] = {0.f, 0.f, 0.f};
    int par = 0;

    for (int ii = 0; ii < nun; ii++) {
        const int i = sm.unrows[ii];
        float s_[KS] = {1e30f, 1e30f, 1e30f};
        int usedm = (c_[2] < QN) ? 0 : 4;
        int j0 = -1, i0 = i, jf;
        float off = 0.f;

        for (;;) {
            #pragma unroll
            for (int k = 0; k < KS; k++)
                if (j0 == c_[k]) usedm |= 1 << k;

            const float ui0p = sm.u[i0] - off;
            const int   trow = i0 - 1;

            float lm = 1e30f; int lidx = 0x7fffffff;
            #pragma unroll
            for (int k = 0; k < KS; k++) {
                if (!((usedm >> k) & 1)) {
                    float cur = g_tile[bi][c_[k]][trow] - ui0p - v_[k];
                    if (cur < s_[k]) { s_[k] = cur; sm.way[c_[k]] = j0; }
                    if (s_[k] < lm) { lm = s_[k]; lidx = c_[k]; }
                }
            }
            unsigned mu   = fmap(lm);
            unsigned wmin = __reduce_min_sync(~0u, mu);
            unsigned cand = (mu == wmin) ? (unsigned)lidx : 0xffffffffu;
            unsigned widx = __reduce_min_sync(~0u, cand);
            if (lane == 0)
                sm.red[par][warp] = ((unsigned long long)wmin << 32) | widx;
            __syncthreads();
            unsigned long long bp = sm.red[par][0];
            #pragma unroll
            for (int w = 1; w < NW; w++) bp = min(bp, sm.red[par][w]);
            par ^= 1;
            off = funmap((unsigned)(bp >> 32));
            const int bj = (int)(unsigned)bp;
            const int prj = sm.p[bj];
            if (prj == 0) { jf = bj; break; }
            i0 = prj; j0 = bj;
        }

        #pragma unroll
        for (int k = 0; k < KS; k++) {
            if (((usedm >> k) & 1) && c_[k] < QN) {
                float dv = off - s_[k];
                v_[k] -= dv;
                sm.u[sm.p[c_[k]]] += dv;
            }
        }
        __syncthreads();
        if (tid == 0) {
            sm.u[i] += off;
            int j = jf;
            for (;;) {
                int jp = sm.way[j];
                sm.p[j] = (jp < 0) ? i : sm.p[jp];
                if (jp < 0) break;
                j = jp;
            }
        }
        __syncthreads();
    }

    // emit: compact assigned pairs, rank by column, write
    if (tid == 0) sm.cnt = 0;
    __syncthreads();
    #pragma unroll
    for (int k = 0; k < KS; k++) {
        int q = c_[k];
        if (q < QN && sm.p[q]) {
            int tt = atomicAdd(&sm.cnt, 1);
            sm.sq[tt] = q;
            sm.sr[tt] = sm.p[q] - 1;
        }
    }
    __syncthreads();
    if (tid < TT) {
        int q = sm.sq[tid], r = sm.sr[tid];
        int rank = 0;
        #pragma unroll
        for (int o = 0; o < TT; o++)
            rank += (__shfl_sync(~0u, q, o) < q) ? 1 : 0;
        float* op = outbase + (size_t)2 * NR * NT + (size_t)which * 2 * NT; // ps/po
        float* ot = op + NT;                                                // ts/to
        op[b * TT + rank] = (float)q;
        ot[b * TT + rank] = (float)r;
    }
}

// ---------------------------------------------------------------------------
// Fused kernel: blocks [0,64) = match (wave-1, hidden under cost), rest cost.
// ---------------------------------------------------------------------------
__global__ __launch_bounds__(CTH, 4) void fused_kernel(
    const float* __restrict__ lg0, const float* __restrict__ lg1,
    const float* __restrict__ bx0, const float* __restrict__ bx1,
    const float* __restrict__ tb0, const float* __restrict__ tb1,
    const int*   __restrict__ id0, const int*   __restrict__ id1,
    float* __restrict__ out)
{
    extern __shared__ unsigned char smem_raw[];
    const int bi = blockIdx.x;

    if (bi < NMATCH) {
        const int b = bi & 31, which = bi >> 5;
        run_match(*reinterpret_cast<MatchSmem*>(smem_raw), bi, b, which,
                  which ? lg1 : lg0, which ? bx1 : bx0,
                  which ? tb1 : tb0, which ? id1 : id0, out);
    } else {
        const int cb = bi - NMATCH;
        const int which = cb / NCOSTB, xb = cb % NCOSTB;
        run_cost(*reinterpret_cast<CostSmem*>(smem_raw), xb, which,
                 which ? lg1 : lg0, which ? bx1 : bx0,
                 which ? tb1 : tb0, which ? id1 : id0, out);
    }
}

// ---------------------------------------------------------------------------
extern "C" void kernel_launch(void* const* d_in, const int* in_sizes, int n_in,
                              void* d_out, int out_size) {
    const float* lg0 = (const float*)d_in[0];
    const float* lg1 = (const float*)d_in[1];
    const float* bx0 = (const float*)d_in[2];
    const float* bx1 = (const float*)d_in[3];
    const float* tb0 = (const float*)d_in[4];
    const float* tb1 = (const float*)d_in[5];
    const int*   id0 = (const int*)d_in[6];
    const int*   id1 = (const int*)d_in[7];
    float* out = (float*)d_out;

    size_t smem = sizeof(CostSmem) > sizeof(MatchSmem)
                ? sizeof(CostSmem) : sizeof(MatchSmem);
    cudaFuncSetAttribute(fused_kernel,
                         cudaFuncAttributeMaxDynamicSharedMemorySize, (int)smem);

    fused_kernel<<<NMATCH + 2 * NCOSTB, CTH, smem>>>(
        lg0, lg1, bx0, bx1, tb0, tb1, id0, id1, out);
}

// round 11
// speedup vs baseline: 1.9562x; 1.0324x over previous
#include <cuda_runtime.h>
#include <math.h>

#define BSZ 32
#define QN  600
#define NC  152
#define TT  32
#define NT  1024          // BSZ*TT
#define NR  19200         // BSZ*QN

#define CTH 256
#define RPW 4
#define NMATCH 64
#define NCOSTB 600        // cost blocks per which: NR / 32

// per-match-block diagonal tile: g_tile[blk][q][t]
__device__ float g_tile[NMATCH][QN][TT];

__device__ __forceinline__ unsigned fmap(float f) {
    unsigned b = __float_as_uint(f);
    return b ^ (unsigned)(((int)b >> 31) | 0x80000000);
}
__device__ __forceinline__ float funmap(unsigned m) {
    return __uint_as_float((m & 0x80000000u) ? (m ^ 0x80000000u) : ~m);
}

struct CostSmem {
    float4 s_box[NT];            // target cxcywh
    float4 s_xy[NT];             // target xyxy
    float2 s_taid[NT];           // {area, id bits}
    float  s_prob[32][NC];
};

#define NW 8
#define KS 3
struct MatchSmem {
    float  u[34];
    unsigned long long s_rm[TT];       // packed per-target rowmin
    unsigned long long red[2][NW];
    int    rowarg[TT];
    int    unrows[TT];
    int    nun_s, cnt;
    int    sq[TT], sr[TT];
    int    way[QN];
    int    p[QN];
    float4 t_box[TT];                  // target cxcywh
    float4 t_xy[TT];                   // target xyxy
    float  t_ta[TT];
    int    t_id[TT];
};

// ---------------------------------------------------------------------------
// cost for one (pred, target) pair.
// enclosing box via identity: wC = ow + tw - (rbx - ltx)  (exact)
// ---------------------------------------------------------------------------
__device__ __forceinline__ float pair_cost(
    float ocx, float ocy, float ow, float oh,
    float ox0, float oy0, float ox1, float oy1, float oarea,
    float tcx, float tcy, float tw, float th,
    float tx0, float ty0, float tx1, float ty1, float ta, float prob)
{
    float l1 = fabsf(ocx - tcx) + fabsf(ocy - tcy)
             + fabsf(ow - tw)  + fabsf(oh - th);
    float ltx = fmaxf(ox0, tx0), lty = fmaxf(oy0, ty0);
    float rbx = fminf(ox1, tx1), rby = fminf(oy1, ty1);
    float iwr = rbx - ltx, ihr = rby - lty;
    float inter = fmaxf(iwr, 0.f) * fmaxf(ihr, 0.f);
    float uni   = oarea + ta - inter;
    float wc = ow + tw - iwr;          // = max(ox1,tx1) - min(ox0,tx0)
    float hc = oh + th - ihr;
    float ac = wc * hc;
    float giou = __fdividef(inter*ac - (ac - uni)*uni, uni*ac);
    return l1 - prob - giou;
}

// ---------------------------------------------------------------------------
// Cost path: 8 warps x 4 rows; targets pre-staged (box, xyxy, {area,id}).
// ---------------------------------------------------------------------------
__device__ void run_cost(
    CostSmem& sm, int xb, int which,
    const float* __restrict__ logits, const float* __restrict__ boxes,
    const float* __restrict__ tbbox,  const int* __restrict__ tids,
    float* __restrict__ out)
{
    float* __restrict__ C = out + (size_t)which * ((size_t)NR * NT);
    const int tid = threadIdx.x;

    for (int j = tid; j < NT; j += CTH) {
        float4 t = *reinterpret_cast<const float4*>(tbbox + (size_t)j * 4);
        sm.s_box[j] = t;
        float x0 = t.x - 0.5f*t.z, y0 = t.y - 0.5f*t.w;
        float x1 = t.x + 0.5f*t.z, y1 = t.y + 0.5f*t.w;
        sm.s_xy[j] = make_float4(x0, y0, x1, y1);
        sm.s_taid[j] = make_float2((x1 - x0) * (y1 - y0),
                                   __int_as_float(tids[j]));
        ;
    }

    const int warp = tid >> 5, lane = tid & 31;
    const int row0 = xb * 32 + warp * RPW;

    float ocx[RPW], ocy[RPW], ow[RPW], oh[RPW];
    float ox0[RPW], oy0[RPW], ox1[RPW], oy1[RPW], oarea[RPW];

    #pragma unroll
    for (int rr = 0; rr < RPW; rr++) {
        const int row = row0 + rr;
        const float* lrow = logits + (size_t)row * NC;
        float r[5], m = -1e30f;
        #pragma unroll
        for (int jj = 0; jj < 5; jj++) {
            int k = lane + 32 * jj;
            r[jj] = (k < NC) ? lrow[k] : -1e30f;
            m = fmaxf(m, r[jj]);
        }
        #pragma unroll
        for (int o = 16; o; o >>= 1) m = fmaxf(m, __shfl_xor_sync(~0u, m, o));
        float s = 0.f;
        #pragma unroll
        for (int jj = 0; jj < 5; jj++) {
            int k = lane + 32 * jj;
            if (k < NC) { r[jj] = __expf(r[jj] - m); s += r[jj]; }
        }
        #pragma unroll
        for (int o = 16; o; o >>= 1) s += __shfl_xor_sync(~0u, s, o);
        const float inv = __fdividef(1.f, s);
        #pragma unroll
        for (int jj = 0; jj < 5; jj++) {
            int k = lane + 32 * jj;
            if (k < NC) sm.s_prob[warp*RPW + rr][k] = r[jj] * inv;
        }
        const float4 pb = *reinterpret_cast<const float4*>(boxes + (size_t)row * 4);
        ocx[rr] = pb.x; ocy[rr] = pb.y; ow[rr] = pb.z; oh[rr] = pb.w;
        ox0[rr] = pb.x - 0.5f*pb.z; oy0[rr] = pb.y - 0.5f*pb.w;
        ox1[rr] = pb.x + 0.5f*pb.z; oy1[rr] = pb.y + 0.5f*pb.w;
        oarea[rr] = (ox1[rr] - ox0[rr]) * (oy1[rr] - oy0[rr]);
    }
    __syncthreads();

    const float* prow0 = sm.s_prob[warp*RPW + 0];
    const float* prow1 = sm.s_prob[warp*RPW + 1];
    const float* prow2 = sm.s_prob[warp*RPW + 2];
    const float* prow3 = sm.s_prob[warp*RPW + 3];

    for (int j = lane; j < NT; j += 32) {
        const float4 tb   = sm.s_box[j];
        const float4 txy  = sm.s_xy[j];
        const float2 taid = sm.s_taid[j];
        const float  ta   = taid.x;
        const int    id   = __float_as_int(taid.y);
        float pr[RPW];
        pr[0] = prow0[id]; pr[1] = prow1[id]; pr[2] = prow2[id]; pr[3] = prow3[id];
        #pragma unroll
        for (int rr = 0; rr < RPW; rr++) {
            float val = pair_cost(ocx[rr], ocy[rr], ow[rr], oh[rr],
                                  ox0[rr], oy0[rr], ox1[rr], oy1[rr], oarea[rr],
                                  tb.x, tb.y, tb.z, tb.w,
                                  txy.x, txy.y, txy.z, txy.w, ta, pr[rr]);
            __stcs(&C[(size_t)(row0 + rr) * NT + j], val);
        }
    }
}

// ---------------------------------------------------------------------------
// Match path: self-computed diag tile -> g_tile, rowmin warm start, exact
// Dijkstra finish, ranked emit. Fully independent of cost blocks.
// ---------------------------------------------------------------------------
__device__ void run_match(
    MatchSmem& sm, int bi, int b, int which,
    const float* __restrict__ logits, const float* __restrict__ boxes,
    const float* __restrict__ tbbox,  const int* __restrict__ tids,
    float* __restrict__ outbase)
{
    const int tid  = threadIdx.x;
    const int warp = tid >> 5, lane = tid & 31;

    if (tid < TT) {
        int j = b * TT + tid;
        float4 t = *reinterpret_cast<const float4*>(tbbox + (size_t)j * 4);
        sm.t_box[tid] = t;
        float x0 = t.x - 0.5f*t.z, y0 = t.y - 0.5f*t.w;
        float x1 = t.x + 0.5f*t.z, y1 = t.y + 0.5f*t.w;
        sm.t_xy[tid] = make_float4(x0, y0, x1, y1);
        sm.t_ta[tid] = (x1 - x0) * (y1 - y0);
        sm.t_id[tid] = tids[j];
        sm.s_rm[tid] = ~0ull;
    }
    for (int j = tid; j < QN; j += CTH) sm.p[j] = 0;
    __syncthreads();

    // build tile: warp per prediction row q; lane = target t
    const int t = lane;
    const float4 tb  = sm.t_box[t];
    const float4 txy = sm.t_xy[t];
    const float  ta  = sm.t_ta[t];
    const int    tclass = sm.t_id[t];
    unsigned long long lmin = ~0ull;

    for (int k = 0; k < QN / NW; k++) {
        const int q = warp + NW * k;
        const float* lrow = logits + (size_t)(b * QN + q) * NC;
        float r[5], m = -1e30f;
        #pragma unroll
        for (int jj = 0; jj < 5; jj++) {
            int kk = lane + 32 * jj;
            r[jj] = (kk < NC) ? lrow[kk] : -1e30f;
            m = fmaxf(m, r[jj]);
        }
        #pragma unroll
        for (int o = 16; o; o >>= 1) m = fmaxf(m, __shfl_xor_sync(~0u, m, o));
        float s = 0.f;
        #pragma unroll
        for (int jj = 0; jj < 5; jj++) {
            int kk = lane + 32 * jj;
            if (kk < NC) s += __expf(r[jj] - m);
        }
        #pragma unroll
        for (int o = 16; o; o >>= 1) s += __shfl_xor_sync(~0u, s, o);
        const float inv = __fdividef(1.f, s);

        const float4 pb = *reinterpret_cast<const float4*>(boxes + (size_t)(b*QN + q)*4);
        const float ox0 = pb.x - 0.5f*pb.z, oy0 = pb.y - 0.5f*pb.w;
        const float ox1 = pb.x + 0.5f*pb.z, oy1 = pb.y + 0.5f*pb.w;
        const float oarea = (ox1 - ox0) * (oy1 - oy0);

        const float prob = __expf(lrow[tclass] - m) * inv;
        const float val = pair_cost(pb.x, pb.y, pb.z, pb.w,
                                    ox0, oy0, ox1, oy1, oarea,
                                    tb.x, tb.y, tb.z, tb.w,
                                    txy.x, txy.y, txy.z, txy.w, ta, prob);
        g_tile[bi][q][t] = val;                       // lanes t consecutive
        unsigned long long key = ((unsigned long long)fmap(val) << 32) | (unsigned)q;
        lmin = min(lmin, key);
    }
    atomicMin(&sm.s_rm[lane], lmin);                  // distinct addrs per lane
    __syncthreads();

    if (tid < TT) {
        unsigned long long key = sm.s_rm[tid];
        sm.u[tid + 1]  = funmap((unsigned)(key >> 32));
        sm.rowarg[tid] = (int)(unsigned)key;
    }
    __syncthreads();

    // greedy tight-edge warm start
    if (tid == 0) {
        int nun = 0;
        for (int i = 1; i <= TT; i++) {
            int q = sm.rowarg[i - 1];
            if (sm.p[q] == 0) sm.p[q] = i;
            else sm.unrows[nun++] = i;
        }
        sm.nun_s = nun;
    }
    __syncthreads();
    const int nun = sm.nun_s;

    // shortest augmenting paths; tile rows read from L1/L2 (just written here)
    const int c_[KS] = { tid, tid + CTH, tid + 2 * CTH };
    float v_[KS] = {0.f, 0.f, 0.f};
    int par = 0;

    for (int ii = 0; ii < nun; ii++) {
        const int i = sm.unrows[ii];
        float s_[KS] = {1e30f, 1e30f, 1e30f};
        int usedm = (c_[2] < QN) ? 0 : 4;
        int j0 = -1, i0 = i, jf;
        float off = 0.f;

        for (;;) {
            #pragma unroll
            for (int k = 0; k < KS; k++)
                if (j0 == c_[k]) usedm |= 1 << k;

            const float ui0p = sm.u[i0] - off;
            const int   trow = i0 - 1;

            float lm = 1e30f; int lidx = 0x7fffffff;
            #pragma unroll
            for (int k = 0; k < KS; k++) {
                if (!((usedm >> k) & 1)) {
                    float cur = g_tile[bi][c_[k]][trow] - ui0p - v_[k];
                    if (cur < s_[k]) { s_[k] = cur; sm.way[c_[k]] = j0; }
                    if (s_[k] < lm) { lm = s_[k]; lidx = c_[k]; }
                }
            }
            unsigned mu   = fmap(lm);
            unsigned wmin = __reduce_min_sync(~0u, mu);
            unsigned cand = (mu == wmin) ? (unsigned)lidx : 0xffffffffu;
            unsigned widx = __reduce_min_sync(~0u, cand);
            if (lane == 0)
                sm.red[par][warp] = ((unsigned long long)wmin << 32) | widx;
            __syncthreads();
            unsigned long long bp = sm.red[par][0];
            #pragma unroll
            for (int w = 1; w < NW; w++) bp = min(bp, sm.red[par][w]);
            par ^= 1;
            off = funmap((unsigned)(bp >> 32));
            const int bj = (int)(unsigned)bp;
            const int prj = sm.p[bj];
            if (prj == 0) { jf = bj; break; }
            i0 = prj; j0 = bj;
        }

        #pragma unroll
        for (int k = 0; k < KS; k++) {
            if (((usedm >> k) & 1) && c_[k] < QN) {
                float dv = off - s_[k];
                v_[k] -= dv;
                sm.u[sm.p[c_[k]]] += dv;
            }
        }
        __syncthreads();
        if (tid == 0) {
            sm.u[i] += off;
            int j = jf;
            for (;;) {
                int jp = sm.way[j];
                sm.p[j] = (jp < 0) ? i : sm.p[jp];
                if (jp < 0) break;
                j = jp;
            }
        }
        __syncthreads();
    }

    // emit: compact assigned pairs, rank by column, write
    if (tid == 0) sm.cnt = 0;
    __syncthreads();
    #pragma unroll
    for (int k = 0; k < KS; k++) {
        int q = c_[k];
        if (q < QN && sm.p[q]) {
            int tt = atomicAdd(&sm.cnt, 1);
            sm.sq[tt] = q;
            sm.sr[tt] = sm.p[q] - 1;
        }
    }
    __syncthreads();
    if (tid < TT) {
        int q = sm.sq[tid], r = sm.sr[tid];
        int rank = 0;
        #pragma unroll
        for (int o = 0; o < TT; o++)
            rank += (__shfl_sync(~0u, q, o) < q) ? 1 : 0;
        float* op = outbase + (size_t)2 * NR * NT + (size_t)which * 2 * NT; // ps/po
        float* ot = op + NT;                                                // ts/to
        op[b * TT + rank] = (float)q;
        ot[b * TT + rank] = (float)r;
    }
}

// ---------------------------------------------------------------------------
// Fused kernel: blocks [0,64) = match (wave-1, hidden under cost), rest cost.
// ---------------------------------------------------------------------------
__global__ __launch_bounds__(CTH, 4) void fused_kernel(
    const float* __restrict__ lg0, const float* __restrict__ lg1,
    const float* __restrict__ bx0, const float* __restrict__ bx1,
    const float* __restrict__ tb0, const float* __restrict__ tb1,
    const int*   __restrict__ id0, const int*   __restrict__ id1,
    float* __restrict__ out)
{
    extern __shared__ unsigned char smem_raw[];
    const int bi = blockIdx.x;

    if (bi < NMATCH) {
        const int b = bi & 31, which = bi >> 5;
        run_match(*reinterpret_cast<MatchSmem*>(smem_raw), bi, b, which,
                  which ? lg1 : lg0, which ? bx1 : bx0,
                  which ? tb1 : tb0, which ? id1 : id0, out);
    } else {
        const int cb = bi - NMATCH;
        const int which = cb / NCOSTB, xb = cb % NCOSTB;
        run_cost(*reinterpret_cast<CostSmem*>(smem_raw), xb, which,
                 which ? lg1 : lg0, which ? bx1 : bx0,
                 which ? tb1 : tb0, which ? id1 : id0, out);
    }
}

// ---------------------------------------------------------------------------
extern "C" void kernel_launch(void* const* d_in, const int* in_sizes, int n_in,
                              void* d_out, int out_size) {
    const float* lg0 = (const float*)d_in[0];
    const float* lg1 = (const float*)d_in[1];
    const float* bx0 = (const float*)d_in[2];
    const float* bx1 = (const float*)d_in[3];
    const float* tb0 = (const float*)d_in[4];
    const float* tb1 = (const float*)d_in[5];
    const int*   id0 = (const int*)d_in[6];
    const int*   id1 = (const int*)d_in[7];
    float* out = (float*)d_out;

    size_t smem = sizeof(CostSmem) > sizeof(MatchSmem)
                ? sizeof(CostSmem) : sizeof(MatchSmem);
    cudaFuncSetAttribute(fused_kernel,
                         cudaFuncAttributeMaxDynamicSharedMemorySize, (int)smem);

    fused_kernel<<<NMATCH + 2 * NCOSTB, CTH, smem>>>(
        lg0, lg1, bx0, bx1, tb0, tb1, id0, id1, out);
}